// round 12
// baseline (speedup 1.0000x reference)
#include <cuda_runtime.h>
#include <cstdint>

// out[b, f] = (medians[f] > 0 && inputs[b, f] >= medians[f]) ? 1.0f : 0.0f
// inputs: 8192 x 4096 fp32 (134 MB streamed), medians: 4096 fp32,
// output: float32 (134 MB streamed).
//
// R9 kernel sustains ~7.15 TB/s effective (~89% of spec) — at the mixed
// 2:1 read/write HBM roofline. This round: scheduling-granularity probe,
// 2048 blocks x 512 threads (block owns a HALF row), 8-deep batched loads,
// streaming hints, register-resident medians. Row-group-major block order:
// rg varies fastest so the in-flight wave covers a dense contiguous band
// of rows (R8 showed scattered in-flight footprints hurt).

#define ROW4   1024   // float4 per row (4096 floats)
#define TPB    512    // threads per block = float4 columns per block
#define RGRP   8      // rows per block
#define NROWS  8192
#define NRG    (NROWS / RGRP)   // 1024 row groups

__device__ __forceinline__ float4 cmp4(float4 a, float4 m) {
    float4 r;
    r.x = (m.x > 0.0f && a.x >= m.x) ? 1.0f : 0.0f;
    r.y = (m.y > 0.0f && a.y >= m.y) ? 1.0f : 0.0f;
    r.z = (m.z > 0.0f && a.z >= m.z) ? 1.0f : 0.0f;
    r.w = (m.w > 0.0f && a.w >= m.w) ? 1.0f : 0.0f;
    return r;
}

__global__ void __launch_bounds__(TPB)
binarize_kernel(const float4* __restrict__ in,
                const float4* __restrict__ med,
                float4* __restrict__ out) {
    // Row-group-major: rg varies fastest across blockIdx, cg slowest.
    unsigned rg   = blockIdx.x & (NRG - 1u);   // row group (fast)
    unsigned cg   = blockIdx.x >> 10;          // which half of the row (slow)
    unsigned col4 = cg * TPB + threadIdx.x;
    size_t   base = (size_t)rg * RGRP * ROW4 + col4;

    const float4 m = med[col4];                // register-resident across rows

    // All 8 rows' loads issued before any store (8-deep MLP).
    float4 a0 = __ldcs(&in[base + 0 * ROW4]);
    float4 a1 = __ldcs(&in[base + 1 * ROW4]);
    float4 a2 = __ldcs(&in[base + 2 * ROW4]);
    float4 a3 = __ldcs(&in[base + 3 * ROW4]);

    size_t nb = base + 4 * (size_t)ROW4;
    float4 b0 = __ldcs(&in[nb + 0 * ROW4]);
    float4 b1 = __ldcs(&in[nb + 1 * ROW4]);
    float4 b2 = __ldcs(&in[nb + 2 * ROW4]);
    float4 b3 = __ldcs(&in[nb + 3 * ROW4]);

    __stcs(&out[base + 0 * ROW4], cmp4(a0, m));
    __stcs(&out[base + 1 * ROW4], cmp4(a1, m));
    __stcs(&out[base + 2 * ROW4], cmp4(a2, m));
    __stcs(&out[base + 3 * ROW4], cmp4(a3, m));

    __stcs(&out[nb + 0 * ROW4], cmp4(b0, m));
    __stcs(&out[nb + 1 * ROW4], cmp4(b1, m));
    __stcs(&out[nb + 2 * ROW4], cmp4(b2, m));
    __stcs(&out[nb + 3 * ROW4], cmp4(b3, m));
}

extern "C" void kernel_launch(void* const* d_in, const int* in_sizes, int n_in,
                              void* d_out, int out_size) {
    // Defensive: larger tensor = inputs, smaller = medians.
    int ii = 0, mi = 1;
    if (n_in >= 2 && in_sizes[1] > in_sizes[0]) { ii = 1; mi = 0; }

    const float4* in  = (const float4*)d_in[ii];
    const float4* med = (const float4*)d_in[mi];
    float4* out = (float4*)d_out;

    // 2 col-groups x 1024 row-groups = 2048 blocks of 512 threads.
    unsigned grid = 2u * NRG;
    binarize_kernel<<<grid, TPB>>>(in, med, out);
}

// round 13
// speedup vs baseline: 1.0447x; 1.0447x over previous
#include <cuda_runtime.h>
#include <cstdint>

// out[b, f] = (medians[f] > 0 && inputs[b, f] >= medians[f]) ? 1.0f : 0.0f
// inputs: 8192 x 4096 fp32 (134 MB streamed), medians: 4096 fp32,
// output: float32 (134 MB streamed).
//
// FINAL (R9 configuration — fastest measured: 45.4us end-to-end, 37.5us
// kernel, ~7.15 TB/s effective = ~89% of spec HBM for this mixed 2:1
// read/write stream; the machine floor per R6-R12 sweeps).
//   - Column-tiled: block of 256 threads owns 256 consecutive float4
//     columns (quarter row) -> every warp LDG.128/STG.128 covers 512
//     contiguous bytes (minimum L1 wavefronts).
//   - Median float4 register-resident per thread (one load per 8 rows).
//   - All 8 rows' loads batched before any store (8-deep MLP).
//   - __ldcs/__stcs streaming hints: zero-reuse streams, evict-first.

#define ROW4   1024   // float4 per row (4096 floats)
#define COLS4  256    // float4 columns per block (= blockDim.x)
#define RGRP   8      // rows per block
#define NROWS  8192

__device__ __forceinline__ float4 cmp4(float4 a, float4 m) {
    float4 r;
    r.x = (m.x > 0.0f && a.x >= m.x) ? 1.0f : 0.0f;
    r.y = (m.y > 0.0f && a.y >= m.y) ? 1.0f : 0.0f;
    r.z = (m.z > 0.0f && a.z >= m.z) ? 1.0f : 0.0f;
    r.w = (m.w > 0.0f && a.w >= m.w) ? 1.0f : 0.0f;
    return r;
}

__global__ void __launch_bounds__(COLS4)
binarize_kernel(const float4* __restrict__ in,
                const float4* __restrict__ med,
                float4* __restrict__ out) {
    // 4 column-groups per row; row-groups in the upper grid bits.
    unsigned cg   = blockIdx.x & 3u;           // quarter of the row
    unsigned rg   = blockIdx.x >> 2;           // row group
    unsigned col4 = cg * COLS4 + threadIdx.x;
    size_t   base = (size_t)rg * RGRP * ROW4 + col4;

    const float4 m = med[col4];                // register-resident across rows

    // Rows 0..3 in flight.
    float4 a0 = __ldcs(&in[base + 0 * ROW4]);
    float4 a1 = __ldcs(&in[base + 1 * ROW4]);
    float4 a2 = __ldcs(&in[base + 2 * ROW4]);
    float4 a3 = __ldcs(&in[base + 3 * ROW4]);

    // Rows 4..7 loaded BEFORE storing rows 0..3 (stores never wait on
    // freshly-issued loads).
    size_t nb = base + 4 * (size_t)ROW4;
    float4 b0 = __ldcs(&in[nb + 0 * ROW4]);
    float4 b1 = __ldcs(&in[nb + 1 * ROW4]);
    float4 b2 = __ldcs(&in[nb + 2 * ROW4]);
    float4 b3 = __ldcs(&in[nb + 3 * ROW4]);

    __stcs(&out[base + 0 * ROW4], cmp4(a0, m));
    __stcs(&out[base + 1 * ROW4], cmp4(a1, m));
    __stcs(&out[base + 2 * ROW4], cmp4(a2, m));
    __stcs(&out[base + 3 * ROW4], cmp4(a3, m));

    __stcs(&out[nb + 0 * ROW4], cmp4(b0, m));
    __stcs(&out[nb + 1 * ROW4], cmp4(b1, m));
    __stcs(&out[nb + 2 * ROW4], cmp4(b2, m));
    __stcs(&out[nb + 3 * ROW4], cmp4(b3, m));
}

extern "C" void kernel_launch(void* const* d_in, const int* in_sizes, int n_in,
                              void* d_out, int out_size) {
    // Defensive: larger tensor = inputs, smaller = medians.
    int ii = 0, mi = 1;
    if (n_in >= 2 && in_sizes[1] > in_sizes[0]) { ii = 1; mi = 0; }

    const float4* in  = (const float4*)d_in[ii];
    const float4* med = (const float4*)d_in[mi];
    float4* out = (float4*)d_out;

    // 4 col-groups x (8192 / RGRP) row-groups = 4096 blocks of 256 threads.
    unsigned grid = 4u * (NROWS / RGRP);
    binarize_kernel<<<grid, COLS4>>>(in, med, out);
}